// round 3
// baseline (speedup 1.0000x reference)
#include <cuda_runtime.h>

#define NN 100000
#define EE 1600000
#define RR 3
#define FF 128
#define HH 64
#define OO 32
#define BB 50000
#define SCAN_BLKS ((NN + 1023) / 1024)

// ---------------- scratch ----------------
struct ZeroBlk {            // zeroed with ONE memset per relation
    int   deg[NN];
    int   sync;
    float stats1[2 * HH];
    float stats2[2 * OO];
};
__device__ ZeroBlk g_z;
__device__ float g_h1[NN * HH];
__device__ float g_x1[NN * HH];
__device__ float g_h2[NN * OO];
__device__ float g_x2[NN * OO];
__device__ float g_dinv[NN];
__device__ int   g_rowstart[NN];
__device__ int   g_cursor[NN];
__device__ int   g_bsums[SCAN_BLKS];
__device__ int   g_csr_src[EE];
__device__ float g_csr_norm[EE];
__device__ float g_bn[2 * HH];

// ---------------- f32x2 helpers ----------------
__device__ __forceinline__ unsigned long long fma2(
    unsigned long long a, unsigned long long b, unsigned long long c)
{
    unsigned long long d;
    asm("fma.rn.f32x2 %0, %1, %2, %3;" : "=l"(d) : "l"(a), "l"(b), "l"(c));
    return d;
}
__device__ __forceinline__ unsigned long long pack2(float x, float y)
{
    unsigned long long d;
    asm("mov.b64 %0, {%1,%2};" : "=l"(d) : "f"(x), "f"(y));
    return d;
}

// ---------------- GEMM: Y[n,C] = act(X)[n,K] @ W[K,C] + b  (f32x2 packed) ----
template <int K, int C, bool FUSE>
__global__ __launch_bounds__(256) void gemm_kernel(
    const float* __restrict__ X, const float* __restrict__ Wg,
    const float* __restrict__ bg, const float* __restrict__ bnp,
    float* __restrict__ Y, int nrows)
{
    constexpr int CPG = C / 4;        // channels per thread
    constexpr int NACC = CPG / 2;     // packed accumulators
    __shared__ float sW[K * C];
    __shared__ float sBN[2 * K];
    int tid = threadIdx.x;
    for (int i = tid; i < K * C / 4; i += 256)
        ((float4*)sW)[i] = ((const float4*)Wg)[i];
    if (FUSE) {
        for (int i = tid; i < 2 * K; i += 256) sBN[i] = __ldg(bnp + i);
    }
    __syncthreads();

    int cg = tid & 3;
    int nl = tid >> 2;
    int row = blockIdx.x * 64 + nl;
    if (row >= nrows) return;

    unsigned long long acc2[NACC];
    const unsigned long long* bp =
        (const unsigned long long*)(bg + cg * CPG);
#pragma unroll
    for (int j = 0; j < NACC; j++) acc2[j] = __ldg(bp + j);

    const float4* Xr = (const float4*)(X + (size_t)row * K);
#pragma unroll 4
    for (int k4 = 0; k4 < K / 4; k4++) {
        float4 xv = __ldg(Xr + k4);
        float xs[4] = {xv.x, xv.y, xv.z, xv.w};
#pragma unroll
        for (int cc = 0; cc < 4; cc++) {
            int k = k4 * 4 + cc;
            float x = xs[cc];
            if (FUSE) x = fmaxf(0.f, fmaf(x, sBN[k], sBN[K + k]));
            unsigned long long xx = pack2(x, x);
            const ulonglong2* wrow =
                (const ulonglong2*)(sW + k * C + cg * CPG);
#pragma unroll
            for (int j2 = 0; j2 < NACC / 2; j2++) {
                ulonglong2 wv = wrow[j2];
                acc2[2 * j2]     = fma2(xx, wv.x, acc2[2 * j2]);
                acc2[2 * j2 + 1] = fma2(xx, wv.y, acc2[2 * j2 + 1]);
            }
        }
    }

    ulonglong2* Yr = (ulonglong2*)(Y + (size_t)row * C + cg * CPG);
#pragma unroll
    for (int j2 = 0; j2 < NACC / 2; j2++) {
        ulonglong2 o;
        o.x = acc2[2 * j2];
        o.y = acc2[2 * j2 + 1];
        Yr[j2] = o;
    }
}

// ---------------- degree (int4 vectorized) ----------------
__global__ __launch_bounds__(256) void degree_kernel(
    const int* __restrict__ dst, int* __restrict__ deg)
{
    int e4 = blockIdx.x * blockDim.x + threadIdx.x;
    if (e4 < EE / 4) {
        int4 d = __ldg((const int4*)dst + e4);
        atomicAdd(deg + d.x, 1);
        atomicAdd(deg + d.y, 1);
        atomicAdd(deg + d.z, 1);
        atomicAdd(deg + d.w, 1);
    }
}

// ---------------- fused scan: dinv + exclusive prefix + cursor init --------
// 98 blocks (< 148 SMs => single wave): spin-sync on counter is safe.
__global__ __launch_bounds__(1024) void scan_fused(
    const int* __restrict__ deg, float* __restrict__ dinv,
    int* __restrict__ rowstart, int* __restrict__ cursor,
    int* __restrict__ bsums, int* __restrict__ sync)
{
    __shared__ int sh[1024];
    __shared__ int sprefix;
    int tid = threadIdx.x;
    int i = blockIdx.x * 1024 + tid;
    int v = (i < NN) ? deg[i] : 0;
    if (i < NN) dinv[i] = rsqrtf(fmaxf((float)v, 1.0f));
    sh[tid] = v;
    if (tid == 0) sprefix = 0;
    __syncthreads();
#pragma unroll
    for (int off = 1; off < 1024; off <<= 1) {
        int t = (tid >= off) ? sh[tid - off] : 0;
        __syncthreads();
        sh[tid] += t;
        __syncthreads();
    }
    int incl = sh[tid];
    if (tid == 1023) {
        bsums[blockIdx.x] = incl;
        __threadfence();
        atomicAdd(sync, 1);
    }
    if (tid == 0) {
        while (*(volatile int*)sync < (int)gridDim.x) {}
        __threadfence();
    }
    __syncthreads();
    if (tid < (int)blockIdx.x) {
        atomicAdd(&sprefix, __ldcg(bsums + tid));
    }
    __syncthreads();
    if (i < NN) {
        int out = incl - v + sprefix;   // exclusive + block prefix
        rowstart[i] = out;
        cursor[i] = out;
    }
}

// ---------------- fill CSR ----------------
__global__ __launch_bounds__(256) void fill_csr(
    const int* __restrict__ src, const int* __restrict__ dst,
    const float* __restrict__ dinv, int* __restrict__ cursor,
    int* __restrict__ csr_src, float* __restrict__ csr_norm)
{
    int e = blockIdx.x * blockDim.x + threadIdx.x;
    if (e >= EE) return;
    int s = __ldg(src + e);
    int d = __ldg(dst + e);
    int pos = atomicAdd(cursor + d, 1);
    csr_src[pos] = s;
    csr_norm[pos] = __ldg(dinv + s) * __ldg(dinv + d);
}

// ---------------- fused gather + combine + BN stats ----------------
template <int C>
__global__ __launch_bounds__(256) void gather_combine(
    const float* __restrict__ h, const int* __restrict__ csr_src,
    const float* __restrict__ csr_norm, const int* __restrict__ row_start,
    const int* __restrict__ deg, const float* __restrict__ gammaArr, int r,
    float* __restrict__ x, float* __restrict__ stats)
{
    constexpr int GPN = C / 4;
    constexpr int NPB = 256 / GPN;
    __shared__ float sstats[2 * C];
    int tid = threadIdx.x;
    for (int i = tid; i < 2 * C; i += 256) sstats[i] = 0.f;
    __syncthreads();

    int g = tid & (GPN - 1);
    int nl = tid / GPN;
    int node = blockIdx.x * NPB + nl;

    if (node < NN) {
        float gamma = __ldg(gammaArr + r);
        float og = 1.0f - gamma;
        int start = __ldg(row_start + node);
        int end = start + __ldg(deg + node);
        float4 acc = make_float4(0.f, 0.f, 0.f, 0.f);

        int e = start;
        for (; e + 4 <= end; e += 4) {
            int s0 = __ldg(csr_src + e);
            int s1 = __ldg(csr_src + e + 1);
            int s2 = __ldg(csr_src + e + 2);
            int s3 = __ldg(csr_src + e + 3);
            float n0 = __ldg(csr_norm + e);
            float n1 = __ldg(csr_norm + e + 1);
            float n2 = __ldg(csr_norm + e + 2);
            float n3 = __ldg(csr_norm + e + 3);
            float4 v0 = __ldg((const float4*)(h + (size_t)s0 * C) + g);
            float4 v1 = __ldg((const float4*)(h + (size_t)s1 * C) + g);
            float4 v2 = __ldg((const float4*)(h + (size_t)s2 * C) + g);
            float4 v3 = __ldg((const float4*)(h + (size_t)s3 * C) + g);
            acc.x = fmaf(n0, v0.x, acc.x); acc.y = fmaf(n0, v0.y, acc.y);
            acc.z = fmaf(n0, v0.z, acc.z); acc.w = fmaf(n0, v0.w, acc.w);
            acc.x = fmaf(n1, v1.x, acc.x); acc.y = fmaf(n1, v1.y, acc.y);
            acc.z = fmaf(n1, v1.z, acc.z); acc.w = fmaf(n1, v1.w, acc.w);
            acc.x = fmaf(n2, v2.x, acc.x); acc.y = fmaf(n2, v2.y, acc.y);
            acc.z = fmaf(n2, v2.z, acc.z); acc.w = fmaf(n2, v2.w, acc.w);
            acc.x = fmaf(n3, v3.x, acc.x); acc.y = fmaf(n3, v3.y, acc.y);
            acc.z = fmaf(n3, v3.z, acc.z); acc.w = fmaf(n3, v3.w, acc.w);
        }
        for (; e < end; e++) {
            int s = __ldg(csr_src + e);
            float n = __ldg(csr_norm + e);
            float4 v = __ldg((const float4*)(h + (size_t)s * C) + g);
            acc.x = fmaf(n, v.x, acc.x); acc.y = fmaf(n, v.y, acc.y);
            acc.z = fmaf(n, v.z, acc.z); acc.w = fmaf(n, v.w, acc.w);
        }

        float4 hv = __ldg((const float4*)(h + (size_t)node * C) + g);
        float4 xv;
        xv.x = fmaf(gamma, acc.x, og * hv.x);
        xv.y = fmaf(gamma, acc.y, og * hv.y);
        xv.z = fmaf(gamma, acc.z, og * hv.z);
        xv.w = fmaf(gamma, acc.w, og * hv.w);
        ((float4*)(x + (size_t)node * C))[g] = xv;

        int c0 = g * 4;
        atomicAdd(&sstats[c0 + 0], xv.x);
        atomicAdd(&sstats[c0 + 1], xv.y);
        atomicAdd(&sstats[c0 + 2], xv.z);
        atomicAdd(&sstats[c0 + 3], xv.w);
        atomicAdd(&sstats[C + c0 + 0], xv.x * xv.x);
        atomicAdd(&sstats[C + c0 + 1], xv.y * xv.y);
        atomicAdd(&sstats[C + c0 + 2], xv.z * xv.z);
        atomicAdd(&sstats[C + c0 + 3], xv.w * xv.w);
    }
    __syncthreads();
    for (int i = tid; i < 2 * C; i += 256) atomicAdd(&stats[i], sstats[i]);
}

// ---------------- fold BN into affine (a,b) ----------------
template <int C>
__global__ void finalize_bn(const float* __restrict__ stats,
                            const float* __restrict__ scale,
                            const float* __restrict__ bias,
                            float* __restrict__ bn)
{
    int c = threadIdx.x;
    float mean = stats[c] * (1.0f / NN);
    float var = stats[C + c] * (1.0f / NN) - mean * mean;
    float inv = rsqrtf(var + 1e-5f);
    float a = __ldg(scale + c) * inv;
    bn[c] = a;
    bn[C + c] = __ldg(bias + c) - mean * a;
}

// ---------------- gather batch nodes + BN2 + relu + log_softmax ------------
__global__ __launch_bounds__(256) void out_kernel(
    const float* __restrict__ x2, const int* __restrict__ bnodes,
    const float* __restrict__ bn, float* __restrict__ out, int r)
{
    int idx = blockIdx.x * blockDim.x + threadIdx.x;
    int b = idx >> 5;
    int lane = idx & 31;
    if (b >= BB) return;
    int node = __ldg(bnodes + b);
    float v = x2[(size_t)node * OO + lane];
    v = fmaxf(0.f, fmaf(v, bn[lane], bn[OO + lane]));
    float m = v;
#pragma unroll
    for (int o = 16; o; o >>= 1) m = fmaxf(m, __shfl_xor_sync(0xffffffffu, m, o));
    float e = expf(v - m);
    float ssum = e;
#pragma unroll
    for (int o = 16; o; o >>= 1) ssum += __shfl_xor_sync(0xffffffffu, ssum, o);
    out[(size_t)b * (RR * OO) + r * OO + lane] = v - m - logf(ssum);
}

// ---------------- launcher ----------------
extern "C" void kernel_launch(void* const* d_in, const int* in_sizes, int n_in,
                              void* d_out, int out_size)
{
    const float* features    = (const float*)d_in[0];
    const int*   edge_index  = (const int*)d_in[1];
    const int*   batch_nodes = (const int*)d_in[2];
    const float* W1 = (const float*)d_in[3];
    const float* b1 = (const float*)d_in[4];
    const float* W2 = (const float*)d_in[5];
    const float* b2 = (const float*)d_in[6];
    const float* gamma1 = (const float*)d_in[7];
    const float* gamma2 = (const float*)d_in[8];
    const float* bn1s = (const float*)d_in[9];
    const float* bn1b = (const float*)d_in[10];
    const float* bn2s = (const float*)d_in[11];
    const float* bn2b = (const float*)d_in[12];
    float* out = (float*)d_out;

    void *p_z, *p_h1, *p_x1, *p_h2, *p_x2, *p_dinv, *p_rows, *p_cur,
         *p_bs, *p_csrs, *p_csrn, *p_bn;
    cudaGetSymbolAddress(&p_z, g_z);
    cudaGetSymbolAddress(&p_h1, g_h1);
    cudaGetSymbolAddress(&p_x1, g_x1);
    cudaGetSymbolAddress(&p_h2, g_h2);
    cudaGetSymbolAddress(&p_x2, g_x2);
    cudaGetSymbolAddress(&p_dinv, g_dinv);
    cudaGetSymbolAddress(&p_rows, g_rowstart);
    cudaGetSymbolAddress(&p_cur, g_cursor);
    cudaGetSymbolAddress(&p_bs, g_bsums);
    cudaGetSymbolAddress(&p_csrs, g_csr_src);
    cudaGetSymbolAddress(&p_csrn, g_csr_norm);
    cudaGetSymbolAddress(&p_bn, g_bn);

    int*   z_deg    = (int*)p_z;                    // offset 0
    int*   z_sync   = (int*)((char*)p_z + sizeof(int) * NN);
    float* z_stats1 = (float*)((char*)p_z + offsetof(ZeroBlk, stats1));
    float* z_stats2 = (float*)((char*)p_z + offsetof(ZeroBlk, stats2));

    for (int r = 0; r < RR; r++) {
        const int* src = edge_index + (size_t)r * 2 * EE;
        const int* dst = src + EE;

        // 0: zero deg + sync + stats in one go
        cudaMemsetAsync(p_z, 0, sizeof(ZeroBlk));
        // 1: degrees
        degree_kernel<<<(EE / 4 + 255) / 256, 256>>>(dst, z_deg);
        // 2: dinv + exclusive scan + cursor init (grid-synced)
        scan_fused<<<SCAN_BLKS, 1024>>>(z_deg, (float*)p_dinv, (int*)p_rows,
                                        (int*)p_cur, (int*)p_bs, z_sync);
        // 3: fill CSR
        fill_csr<<<(EE + 255) / 256, 256>>>(src, dst, (const float*)p_dinv,
                                            (int*)p_cur, (int*)p_csrs, (float*)p_csrn);
        // 4: conv1 linear
        gemm_kernel<FF, HH, false><<<(NN + 63) / 64, 256>>>(
            features, W1 + (size_t)r * FF * HH, b1 + r * HH, nullptr,
            (float*)p_h1, NN);
        // 5: conv1 aggregate + combine + BN1 stats (fused)  <-- ncu -s 5 lands here
        gather_combine<HH><<<(NN * (HH / 4) + 255) / 256, 256>>>(
            (const float*)p_h1, (const int*)p_csrs, (const float*)p_csrn,
            (const int*)p_rows, z_deg, gamma1, r,
            (float*)p_x1, z_stats1);
        // 6
        finalize_bn<HH><<<1, HH>>>(z_stats1, bn1s + r * HH, bn1b + r * HH,
                                   (float*)p_bn);
        // 7: conv2 linear with fused BN1-apply + relu on input
        gemm_kernel<HH, OO, true><<<(NN + 63) / 64, 256>>>(
            (const float*)p_x1, W2 + (size_t)r * HH * OO, b2 + r * OO,
            (const float*)p_bn, (float*)p_h2, NN);
        // 8: conv2 aggregate + combine + BN2 stats
        gather_combine<OO><<<(NN * (OO / 4) + 255) / 256, 256>>>(
            (const float*)p_h2, (const int*)p_csrs, (const float*)p_csrn,
            (const int*)p_rows, z_deg, gamma2, r,
            (float*)p_x2, z_stats2);
        // 9
        finalize_bn<OO><<<1, OO>>>(z_stats2, bn2s + r * OO, bn2b + r * OO,
                                   (float*)p_bn);
        // 10: gather + BN2-apply + relu + log_softmax
        out_kernel<<<(BB * 32 + 255) / 256, 256>>>(
            (const float*)p_x2, batch_nodes, (const float*)p_bn, out, r);
    }
}

// round 7
// speedup vs baseline: 1.7655x; 1.7655x over previous
#include <cuda_runtime.h>

#define NN 100000
#define EE 1600000
#define RR 3
#define FF 128
#define HH 64
#define OO 32
#define BB 50000
#define SCAN_BLKS ((NN + 1023) / 1024)

typedef unsigned long long ull;

// ---------------- scratch ----------------
struct ZeroBlk {            // zeroed with ONE memset per relation
    int   deg[NN];
    int   sync;
    float stats1[2 * HH];
    float stats2[2 * OO];
};
__device__ ZeroBlk g_z;
__device__ float g_h1[NN * HH];
__device__ float g_x1[NN * HH];
__device__ float g_h2[NN * OO];
__device__ float g_x2[NN * OO];
__device__ float g_dinv[NN];
__device__ int   g_rowstart[NN];
__device__ int   g_cursor[NN];
__device__ int   g_bsums[SCAN_BLKS];
__device__ ull   g_csr[EE];          // packed (src:int low32, norm:float high32)
__device__ float g_bn[2 * HH];

// ---------------- f32x2 helpers ----------------
__device__ __forceinline__ ull fma2(ull a, ull b, ull c)
{
    ull d;
    asm("fma.rn.f32x2 %0, %1, %2, %3;" : "=l"(d) : "l"(a), "l"(b), "l"(c));
    return d;
}
__device__ __forceinline__ ull pack2(float x, float y)
{
    ull d;
    asm("mov.b64 %0, {%1,%2};" : "=l"(d) : "f"(x), "f"(y));
    return d;
}

// ---------------- tiled GEMM: Y[n,C] = act(X)[n,K] @ W[K,C] + b -------------
// Block: 256 rows x C cols. 256 threads = 32 rowgroups(8 rows) x 8 colgroups.
// X tile staged TRANSPOSED in shared: sXT[k][row]. W tile sW[k][c].
// Per k per thread: 2 LDS.128 (8 x-vals) + NC2/2 LDS.128 (cols) -> 8*CPT MACs.
template <int K, int C, bool FUSE>
__global__ __launch_bounds__(256, 2) void gemm_tiled(
    const float* __restrict__ X, const float* __restrict__ Wg,
    const float* __restrict__ bg, const float* __restrict__ bnp,
    float* __restrict__ Y, int nrows)
{
    constexpr int KB = 32;
    constexpr int CPT = C / 8;        // cols per thread (8 or 4)
    constexpr int NC2 = CPT / 2;      // packed col-pairs (4 or 2)
    __shared__ float sXT[KB][256];
    __shared__ float sW[KB][C];

    int tid = threadIdx.x;
    int rg = tid >> 3;                // 0..31
    int cg = tid & 7;                 // 0..7
    int row0 = blockIdx.x * 256;
    int myrow = row0 + tid;
    bool valid = myrow < nrows;

    ull acc[8][NC2];
    {
        const ull* bp = (const ull*)(bg + cg * CPT);
#pragma unroll
        for (int j = 0; j < NC2; j++) {
            ull bv = __ldg(bp + j);
#pragma unroll
            for (int rr = 0; rr < 8; rr++) acc[rr][j] = bv;
        }
    }

    const float4* Xr = (const float4*)(X + (size_t)myrow * K);

    for (int kc = 0; kc < K; kc += KB) {
        // stage W tile (row-major, same layout as global)
        {
            const float4* Wt = (const float4*)(Wg + (size_t)kc * C);
#pragma unroll
            for (int i = tid; i < KB * C / 4; i += 256)
                ((float4*)&sW[0][0])[i] = __ldg(Wt + i);
        }
        // stage X tile transposed; optional folded-BN + relu on load
#pragma unroll
        for (int j4 = 0; j4 < KB / 4; j4++) {
            float4 v = valid ? __ldg(Xr + kc / 4 + j4)
                             : make_float4(0.f, 0.f, 0.f, 0.f);
            if (FUSE) {
                float4 a = __ldg((const float4*)bnp + kc / 4 + j4);
                float4 b = __ldg((const float4*)(bnp + K) + kc / 4 + j4);
                v.x = fmaxf(0.f, fmaf(v.x, a.x, b.x));
                v.y = fmaxf(0.f, fmaf(v.y, a.y, b.y));
                v.z = fmaxf(0.f, fmaf(v.z, a.z, b.z));
                v.w = fmaxf(0.f, fmaf(v.w, a.w, b.w));
            }
            sXT[j4 * 4 + 0][tid] = v.x;
            sXT[j4 * 4 + 1][tid] = v.y;
            sXT[j4 * 4 + 2][tid] = v.z;
            sXT[j4 * 4 + 3][tid] = v.w;
        }
        __syncthreads();

#pragma unroll
        for (int k = 0; k < KB; k++) {
            float x[8];
            *(float4*)&x[0] = *(const float4*)&sXT[k][rg * 8];
            *(float4*)&x[4] = *(const float4*)&sXT[k][rg * 8 + 4];
            ull w2[NC2];
#pragma unroll
            for (int j2 = 0; j2 < NC2 / 2; j2++) {
                ulonglong2 wv = *(const ulonglong2*)&sW[k][cg * CPT + j2 * 4];
                w2[2 * j2] = wv.x;
                w2[2 * j2 + 1] = wv.y;
            }
#pragma unroll
            for (int rr = 0; rr < 8; rr++) {
                ull xx = pack2(x[rr], x[rr]);
#pragma unroll
                for (int j = 0; j < NC2; j++)
                    acc[rr][j] = fma2(xx, w2[j], acc[rr][j]);
            }
        }
        __syncthreads();
    }

#pragma unroll
    for (int rr = 0; rr < 8; rr++) {
        int row = row0 + rg * 8 + rr;
        if (row < nrows) {
            ull* Yp = (ull*)(Y + (size_t)row * C + cg * CPT);
#pragma unroll
            for (int j2 = 0; j2 < NC2 / 2; j2++) {
                ulonglong2 o;
                o.x = acc[rr][2 * j2];
                o.y = acc[rr][2 * j2 + 1];
                *(ulonglong2*)(Yp + 2 * j2) = o;
            }
        }
    }
}

// ---------------- degree (int4 vectorized) ----------------
__global__ __launch_bounds__(256) void degree_kernel(
    const int* __restrict__ dst, int* __restrict__ deg)
{
    int e4 = blockIdx.x * blockDim.x + threadIdx.x;
    if (e4 < EE / 4) {
        int4 d = __ldg((const int4*)dst + e4);
        atomicAdd(deg + d.x, 1);
        atomicAdd(deg + d.y, 1);
        atomicAdd(deg + d.z, 1);
        atomicAdd(deg + d.w, 1);
    }
}

// ---------------- fused scan: dinv + exclusive prefix + cursor init --------
__global__ __launch_bounds__(1024) void scan_fused(
    const int* __restrict__ deg, float* __restrict__ dinv,
    int* __restrict__ rowstart, int* __restrict__ cursor,
    int* __restrict__ bsums, int* __restrict__ sync)
{
    __shared__ int sh[1024];
    __shared__ int sprefix;
    int tid = threadIdx.x;
    int i = blockIdx.x * 1024 + tid;
    int v = (i < NN) ? deg[i] : 0;
    if (i < NN) dinv[i] = rsqrtf(fmaxf((float)v, 1.0f));
    sh[tid] = v;
    if (tid == 0) sprefix = 0;
    __syncthreads();
#pragma unroll
    for (int off = 1; off < 1024; off <<= 1) {
        int t = (tid >= off) ? sh[tid - off] : 0;
        __syncthreads();
        sh[tid] += t;
        __syncthreads();
    }
    int incl = sh[tid];
    if (tid == 1023) {
        bsums[blockIdx.x] = incl;
        __threadfence();
        atomicAdd(sync, 1);
    }
    if (tid == 0) {
        while (*(volatile int*)sync < (int)gridDim.x) {}
        __threadfence();
    }
    __syncthreads();
    if (tid < (int)blockIdx.x) {
        atomicAdd(&sprefix, __ldcg(bsums + tid));
    }
    __syncthreads();
    if (i < NN) {
        int out = incl - v + sprefix;
        rowstart[i] = out;
        cursor[i] = out;
    }
}

// ---------------- fill CSR (packed 8B entries) ----------------
__global__ __launch_bounds__(256) void fill_csr(
    const int* __restrict__ src, const int* __restrict__ dst,
    const float* __restrict__ dinv, int* __restrict__ cursor,
    ull* __restrict__ csr)
{
    int e = blockIdx.x * blockDim.x + threadIdx.x;
    if (e >= EE) return;
    int s = __ldg(src + e);
    int d = __ldg(dst + e);
    int pos = atomicAdd(cursor + d, 1);
    float norm = __ldg(dinv + s) * __ldg(dinv + d);
    csr[pos] = (ull)(unsigned)s | ((ull)__float_as_uint(norm) << 32);
}

// ---------------- fused gather + combine + BN stats ----------------
// GPN lanes per node; edge meta loaded once per GPN edges, shfl-distributed.
template <int C>
__global__ __launch_bounds__(256) void gather_combine(
    const float* __restrict__ h, const ull* __restrict__ csr,
    const int* __restrict__ row_start, const int* __restrict__ deg,
    const float* __restrict__ gammaArr, int r,
    float* __restrict__ x, float* __restrict__ stats)
{
    constexpr int GPN = C / 4;
    constexpr int NPB = 256 / GPN;
    __shared__ float sstats[2 * C];
    int tid = threadIdx.x;
    for (int i = tid; i < 2 * C; i += 256) sstats[i] = 0.f;
    __syncthreads();

    int g = tid & (GPN - 1);
    int node = blockIdx.x * NPB + tid / GPN;
    unsigned gmask = ((1u << GPN) - 1u) << ((tid & 31) & ~(GPN - 1));

    if (node < NN) {
        float gamma = __ldg(gammaArr + r);
        float og = 1.0f - gamma;
        int start = __ldg(row_start + node);
        int d = __ldg(deg + node);
        float4 acc = make_float4(0.f, 0.f, 0.f, 0.f);

        for (int base = 0; base < d; base += GPN) {
            int cnt = min(GPN, d - base);
            ull p = 0;
            if (g < cnt) p = __ldg(csr + start + base + g);
            for (int j = 0; j < cnt; j++) {
                ull pj = __shfl_sync(gmask, p, j, GPN);
                int s = (int)(unsigned)pj;
                float n = __uint_as_float((unsigned)(pj >> 32));
                float4 v = __ldg((const float4*)(h + (size_t)s * C) + g);
                acc.x = fmaf(n, v.x, acc.x);
                acc.y = fmaf(n, v.y, acc.y);
                acc.z = fmaf(n, v.z, acc.z);
                acc.w = fmaf(n, v.w, acc.w);
            }
        }

        float4 hv = __ldg((const float4*)(h + (size_t)node * C) + g);
        float4 xv;
        xv.x = fmaf(gamma, acc.x, og * hv.x);
        xv.y = fmaf(gamma, acc.y, og * hv.y);
        xv.z = fmaf(gamma, acc.z, og * hv.z);
        xv.w = fmaf(gamma, acc.w, og * hv.w);
        ((float4*)(x + (size_t)node * C))[g] = xv;

        int c0 = g * 4;
        atomicAdd(&sstats[c0 + 0], xv.x);
        atomicAdd(&sstats[c0 + 1], xv.y);
        atomicAdd(&sstats[c0 + 2], xv.z);
        atomicAdd(&sstats[c0 + 3], xv.w);
        atomicAdd(&sstats[C + c0 + 0], xv.x * xv.x);
        atomicAdd(&sstats[C + c0 + 1], xv.y * xv.y);
        atomicAdd(&sstats[C + c0 + 2], xv.z * xv.z);
        atomicAdd(&sstats[C + c0 + 3], xv.w * xv.w);
    }
    __syncthreads();
    for (int i = tid; i < 2 * C; i += 256) atomicAdd(&stats[i], sstats[i]);
}

// ---------------- fold BN into affine (a,b) ----------------
template <int C>
__global__ void finalize_bn(const float* __restrict__ stats,
                            const float* __restrict__ scale,
                            const float* __restrict__ bias,
                            float* __restrict__ bn)
{
    int c = threadIdx.x;
    float mean = stats[c] * (1.0f / NN);
    float var = stats[C + c] * (1.0f / NN) - mean * mean;
    float inv = rsqrtf(var + 1e-5f);
    float a = __ldg(scale + c) * inv;
    bn[c] = a;
    bn[C + c] = __ldg(bias + c) - mean * a;
}

// ---------------- gather batch nodes + BN2 + relu + log_softmax ------------
__global__ __launch_bounds__(256) void out_kernel(
    const float* __restrict__ x2, const int* __restrict__ bnodes,
    const float* __restrict__ bn, float* __restrict__ out, int r)
{
    int idx = blockIdx.x * blockDim.x + threadIdx.x;
    int b = idx >> 5;
    int lane = idx & 31;
    if (b >= BB) return;
    int node = __ldg(bnodes + b);
    float v = x2[(size_t)node * OO + lane];
    v = fmaxf(0.f, fmaf(v, bn[lane], bn[OO + lane]));
    float m = v;
#pragma unroll
    for (int o = 16; o; o >>= 1) m = fmaxf(m, __shfl_xor_sync(0xffffffffu, m, o));
    float e = expf(v - m);
    float ssum = e;
#pragma unroll
    for (int o = 16; o; o >>= 1) ssum += __shfl_xor_sync(0xffffffffu, ssum, o);
    out[(size_t)b * (RR * OO) + r * OO + lane] = v - m - logf(ssum);
}

// ---------------- launcher ----------------
extern "C" void kernel_launch(void* const* d_in, const int* in_sizes, int n_in,
                              void* d_out, int out_size)
{
    const float* features    = (const float*)d_in[0];
    const int*   edge_index  = (const int*)d_in[1];
    const int*   batch_nodes = (const int*)d_in[2];
    const float* W1 = (const float*)d_in[3];
    const float* b1 = (const float*)d_in[4];
    const float* W2 = (const float*)d_in[5];
    const float* b2 = (const float*)d_in[6];
    const float* gamma1 = (const float*)d_in[7];
    const float* gamma2 = (const float*)d_in[8];
    const float* bn1s = (const float*)d_in[9];
    const float* bn1b = (const float*)d_in[10];
    const float* bn2s = (const float*)d_in[11];
    const float* bn2b = (const float*)d_in[12];
    float* out = (float*)d_out;

    void *p_z, *p_h1, *p_x1, *p_h2, *p_x2, *p_dinv, *p_rows, *p_cur,
         *p_bs, *p_csr, *p_bn;
    cudaGetSymbolAddress(&p_z, g_z);
    cudaGetSymbolAddress(&p_h1, g_h1);
    cudaGetSymbolAddress(&p_x1, g_x1);
    cudaGetSymbolAddress(&p_h2, g_h2);
    cudaGetSymbolAddress(&p_x2, g_x2);
    cudaGetSymbolAddress(&p_dinv, g_dinv);
    cudaGetSymbolAddress(&p_rows, g_rowstart);
    cudaGetSymbolAddress(&p_cur, g_cursor);
    cudaGetSymbolAddress(&p_bs, g_bsums);
    cudaGetSymbolAddress(&p_csr, g_csr);
    cudaGetSymbolAddress(&p_bn, g_bn);

    int*   z_deg    = (int*)p_z;
    int*   z_sync   = (int*)((char*)p_z + offsetof(ZeroBlk, sync));
    float* z_stats1 = (float*)((char*)p_z + offsetof(ZeroBlk, stats1));
    float* z_stats2 = (float*)((char*)p_z + offsetof(ZeroBlk, stats2));

    const int GEMM_GRID = (NN + 255) / 256;   // 391

    for (int r = 0; r < RR; r++) {
        const int* src = edge_index + (size_t)r * 2 * EE;
        const int* dst = src + EE;

        cudaMemsetAsync(p_z, 0, sizeof(ZeroBlk));
        degree_kernel<<<(EE / 4 + 255) / 256, 256>>>(dst, z_deg);
        scan_fused<<<SCAN_BLKS, 1024>>>(z_deg, (float*)p_dinv, (int*)p_rows,
                                        (int*)p_cur, (int*)p_bs, z_sync);
        fill_csr<<<(EE + 255) / 256, 256>>>(src, dst, (const float*)p_dinv,
                                            (int*)p_cur, (ull*)p_csr);
        // conv1 linear
        gemm_tiled<FF, HH, false><<<GEMM_GRID, 256>>>(
            features, W1 + (size_t)r * FF * HH, b1 + r * HH, nullptr,
            (float*)p_h1, NN);
        // conv1 aggregate + combine + BN1 stats
        gather_combine<HH><<<(NN + 15) / 16, 256>>>(
            (const float*)p_h1, (const ull*)p_csr,
            (const int*)p_rows, z_deg, gamma1, r,
            (float*)p_x1, z_stats1);
        finalize_bn<HH><<<1, HH>>>(z_stats1, bn1s + r * HH, bn1b + r * HH,
                                   (float*)p_bn);
        // conv2 linear with fused BN1-apply + relu on input
        gemm_tiled<HH, OO, true><<<GEMM_GRID, 256>>>(
            (const float*)p_x1, W2 + (size_t)r * HH * OO, b2 + r * OO,
            (const float*)p_bn, (float*)p_h2, NN);
        // conv2 aggregate + combine + BN2 stats
        gather_combine<OO><<<(NN + 31) / 32, 256>>>(
            (const float*)p_h2, (const ull*)p_csr,
            (const int*)p_rows, z_deg, gamma2, r,
            (float*)p_x2, z_stats2);
        finalize_bn<OO><<<1, OO>>>(z_stats2, bn2s + r * OO, bn2b + r * OO,
                                   (float*)p_bn);
        out_kernel<<<(BB * 32 + 255) / 256, 256>>>(
            (const float*)p_x2, batch_nodes, (const float*)p_bn, out, r);
    }
}

// round 9
// speedup vs baseline: 1.8054x; 1.0226x over previous
#include <cuda_runtime.h>
#include <cuda_fp16.h>

#define NN 100000
#define EE 1600000
#define RR 3
#define FF 128
#define HH 64
#define OO 32
#define BB 50000
#define SCAN_BLKS ((NN + 1023) / 1024)

typedef unsigned long long ull;

// ---------------- scratch ----------------
struct ZeroBlk {            // zeroed with ONE memset per relation
    int   deg[NN];
    int   sync;
    float stats1[2 * HH];
    float stats2[2 * OO];
};
__device__ ZeroBlk g_z;
__device__ float  g_h1[NN * HH];
__device__ __half g_h1h[NN * HH];    // fp16 sidecar for gather reads
__device__ float  g_x1[NN * HH];
__device__ float  g_h2[NN * OO];
__device__ __half g_h2h[NN * OO];
__device__ float  g_x2[NN * OO];
__device__ float  g_dinv[NN];
__device__ int    g_rowstart[NN];
__device__ int    g_cursor[NN];
__device__ int    g_bsums[SCAN_BLKS];
__device__ ull    g_csr[EE];         // packed (src:int low32, norm:float high32)
__device__ float  g_bn[2 * HH];

// ---------------- f32x2 helpers ----------------
__device__ __forceinline__ ull fma2(ull a, ull b, ull c)
{
    ull d;
    asm("fma.rn.f32x2 %0, %1, %2, %3;" : "=l"(d) : "l"(a), "l"(b), "l"(c));
    return d;
}
__device__ __forceinline__ ull pack2(float x, float y)
{
    ull d;
    asm("mov.b64 %0, {%1,%2};" : "=l"(d) : "f"(x), "f"(y));
    return d;
}

// ---------------- tiled GEMM: Y = act(X) @ W + b ; also emits fp16 copy ----
template <int K, int C, bool FUSE>
__global__ __launch_bounds__(256, 2) void gemm_tiled(
    const float* __restrict__ X, const float* __restrict__ Wg,
    const float* __restrict__ bg, const float* __restrict__ bnp,
    float* __restrict__ Y, __half* __restrict__ Yh, int nrows)
{
    constexpr int KB = 32;
    constexpr int CPT = C / 8;        // cols per thread (8 or 4)
    constexpr int NC2 = CPT / 2;      // packed col-pairs (4 or 2)
    __shared__ float sXT[KB][256];
    __shared__ float sW[KB][C];

    int tid = threadIdx.x;
    int rg = tid >> 3;                // 0..31
    int cg = tid & 7;                 // 0..7
    int row0 = blockIdx.x * 256;
    int myrow = row0 + tid;
    bool valid = myrow < nrows;

    ull acc[8][NC2];
    {
        const ull* bp = (const ull*)(bg + cg * CPT);
#pragma unroll
        for (int j = 0; j < NC2; j++) {
            ull bv = __ldg(bp + j);
#pragma unroll
            for (int rr = 0; rr < 8; rr++) acc[rr][j] = bv;
        }
    }

    const float4* Xr = (const float4*)(X + (size_t)myrow * K);

    for (int kc = 0; kc < K; kc += KB) {
        {
            const float4* Wt = (const float4*)(Wg + (size_t)kc * C);
#pragma unroll
            for (int i = tid; i < KB * C / 4; i += 256)
                ((float4*)&sW[0][0])[i] = __ldg(Wt + i);
        }
#pragma unroll
        for (int j4 = 0; j4 < KB / 4; j4++) {
            float4 v = valid ? __ldg(Xr + kc / 4 + j4)
                             : make_float4(0.f, 0.f, 0.f, 0.f);
            if (FUSE) {
                float4 a = __ldg((const float4*)bnp + kc / 4 + j4);
                float4 b = __ldg((const float4*)(bnp + K) + kc / 4 + j4);
                v.x = fmaxf(0.f, fmaf(v.x, a.x, b.x));
                v.y = fmaxf(0.f, fmaf(v.y, a.y, b.y));
                v.z = fmaxf(0.f, fmaf(v.z, a.z, b.z));
                v.w = fmaxf(0.f, fmaf(v.w, a.w, b.w));
            }
            sXT[j4 * 4 + 0][tid] = v.x;
            sXT[j4 * 4 + 1][tid] = v.y;
            sXT[j4 * 4 + 2][tid] = v.z;
            sXT[j4 * 4 + 3][tid] = v.w;
        }
        __syncthreads();

#pragma unroll
        for (int k = 0; k < KB; k++) {
            float x[8];
            *(float4*)&x[0] = *(const float4*)&sXT[k][rg * 8];
            *(float4*)&x[4] = *(const float4*)&sXT[k][rg * 8 + 4];
            ull w2[NC2];
#pragma unroll
            for (int j2 = 0; j2 < NC2 / 2; j2++) {
                ulonglong2 wv = *(const ulonglong2*)&sW[k][cg * CPT + j2 * 4];
                w2[2 * j2] = wv.x;
                w2[2 * j2 + 1] = wv.y;
            }
#pragma unroll
            for (int rr = 0; rr < 8; rr++) {
                ull xx = pack2(x[rr], x[rr]);
#pragma unroll
                for (int j = 0; j < NC2; j++)
                    acc[rr][j] = fma2(xx, w2[j], acc[rr][j]);
            }
        }
        __syncthreads();
    }

#pragma unroll
    for (int rr = 0; rr < 8; rr++) {
        int row = row0 + rg * 8 + rr;
        if (row < nrows) {
            // fp32 output
            ull* Yp = (ull*)(Y + (size_t)row * C + cg * CPT);
#pragma unroll
            for (int j2 = 0; j2 < NC2 / 2; j2++) {
                ulonglong2 o;
                o.x = acc[rr][2 * j2];
                o.y = acc[rr][2 * j2 + 1];
                *(ulonglong2*)(Yp + 2 * j2) = o;
            }
            // fp16 sidecar
            unsigned hp[NC2];
#pragma unroll
            for (int j = 0; j < NC2; j++) {
                float lo = __uint_as_float((unsigned)acc[rr][j]);
                float hi = __uint_as_float((unsigned)(acc[rr][j] >> 32));
                __half2 h2 = __floats2half2_rn(lo, hi);
                hp[j] = *(unsigned*)&h2;
            }
            __half* Yhp = Yh + (size_t)row * C + cg * CPT;
            if (NC2 == 4) {
                uint4 o4;
                o4.x = hp[0]; o4.y = hp[1]; o4.z = hp[2]; o4.w = hp[3];
                *(uint4*)Yhp = o4;
            } else {
                uint2 o2;
                o2.x = hp[0]; o2.y = hp[1];
                *(uint2*)Yhp = o2;
            }
        }
    }
}

// ---------------- degree (int4 vectorized) ----------------
__global__ __launch_bounds__(256) void degree_kernel(
    const int* __restrict__ dst, int* __restrict__ deg)
{
    int e4 = blockIdx.x * blockDim.x + threadIdx.x;
    if (e4 < EE / 4) {
        int4 d = __ldg((const int4*)dst + e4);
        atomicAdd(deg + d.x, 1);
        atomicAdd(deg + d.y, 1);
        atomicAdd(deg + d.z, 1);
        atomicAdd(deg + d.w, 1);
    }
}

// ---------------- fused scan: dinv + exclusive prefix + cursor init --------
__global__ __launch_bounds__(1024) void scan_fused(
    const int* __restrict__ deg, float* __restrict__ dinv,
    int* __restrict__ rowstart, int* __restrict__ cursor,
    int* __restrict__ bsums, int* __restrict__ sync)
{
    __shared__ int sh[1024];
    __shared__ int sprefix;
    int tid = threadIdx.x;
    int i = blockIdx.x * 1024 + tid;
    int v = (i < NN) ? deg[i] : 0;
    if (i < NN) dinv[i] = rsqrtf(fmaxf((float)v, 1.0f));
    sh[tid] = v;
    if (tid == 0) sprefix = 0;
    __syncthreads();
#pragma unroll
    for (int off = 1; off < 1024; off <<= 1) {
        int t = (tid >= off) ? sh[tid - off] : 0;
        __syncthreads();
        sh[tid] += t;
        __syncthreads();
    }
    int incl = sh[tid];
    if (tid == 1023) {
        bsums[blockIdx.x] = incl;
        __threadfence();
        atomicAdd(sync, 1);
    }
    if (tid == 0) {
        while (*(volatile int*)sync < (int)gridDim.x) {}
        __threadfence();
    }
    __syncthreads();
    if (tid < (int)blockIdx.x) {
        atomicAdd(&sprefix, __ldcg(bsums + tid));
    }
    __syncthreads();
    if (i < NN) {
        int out = incl - v + sprefix;
        rowstart[i] = out;
        cursor[i] = out;
    }
}

// ---------------- fill CSR (packed 8B entries) ----------------
__global__ __launch_bounds__(256) void fill_csr(
    const int* __restrict__ src, const int* __restrict__ dst,
    const float* __restrict__ dinv, int* __restrict__ cursor,
    ull* __restrict__ csr)
{
    int e = blockIdx.x * blockDim.x + threadIdx.x;
    if (e >= EE) return;
    int s = __ldg(src + e);
    int d = __ldg(dst + e);
    int pos = atomicAdd(cursor + d, 1);
    float norm = __ldg(dinv + s) * __ldg(dinv + d);
    csr[pos] = (ull)(unsigned)s | ((ull)__float_as_uint(norm) << 32);
}

// ---------------- fused gather(fp16 neighbors) + combine + BN stats --------
template <int C>
__global__ __launch_bounds__(256) void gather_combine(
    const float* __restrict__ h, const __half* __restrict__ hh,
    const ull* __restrict__ csr,
    const int* __restrict__ row_start, const int* __restrict__ deg,
    const float* __restrict__ gammaArr, int r,
    float* __restrict__ x, float* __restrict__ stats)
{
    constexpr int GPN = C / 4;
    constexpr int NPB = 256 / GPN;
    __shared__ float sstats[2 * C];
    int tid = threadIdx.x;
    for (int i = tid; i < 2 * C; i += 256) sstats[i] = 0.f;
    __syncthreads();

    int g = tid & (GPN - 1);
    int node = blockIdx.x * NPB + tid / GPN;
    unsigned gmask = ((1u << GPN) - 1u) << ((tid & 31) & ~(GPN - 1));

    if (node < NN) {
        float gamma = __ldg(gammaArr + r);
        float og = 1.0f - gamma;
        int start = __ldg(row_start + node);
        int d = __ldg(deg + node);
        float4 acc = make_float4(0.f, 0.f, 0.f, 0.f);

        for (int base = 0; base < d; base += GPN) {
            int cnt = min(GPN, d - base);
            ull p = 0;
            if (g < cnt) p = __ldg(csr + start + base + g);
            if (cnt == GPN) {
#pragma unroll
                for (int j = 0; j < GPN; j++) {
                    ull pj = __shfl_sync(gmask, p, j, GPN);
                    int s = (int)(unsigned)pj;
                    float n = __uint_as_float((unsigned)(pj >> 32));
                    uint2 hv2 = __ldg((const uint2*)(hh + (size_t)s * C) + g);
                    float2 fa = __half22float2(*(__half2*)&hv2.x);
                    float2 fb = __half22float2(*(__half2*)&hv2.y);
                    acc.x = fmaf(n, fa.x, acc.x);
                    acc.y = fmaf(n, fa.y, acc.y);
                    acc.z = fmaf(n, fb.x, acc.z);
                    acc.w = fmaf(n, fb.y, acc.w);
                }
            } else {
                for (int j = 0; j < cnt; j++) {
                    ull pj = __shfl_sync(gmask, p, j, GPN);
                    int s = (int)(unsigned)pj;
                    float n = __uint_as_float((unsigned)(pj >> 32));
                    uint2 hv2 = __ldg((const uint2*)(hh + (size_t)s * C) + g);
                    float2 fa = __half22float2(*(__half2*)&hv2.x);
                    float2 fb = __half22float2(*(__half2*)&hv2.y);
                    acc.x = fmaf(n, fa.x, acc.x);
                    acc.y = fmaf(n, fa.y, acc.y);
                    acc.z = fmaf(n, fb.x, acc.z);
                    acc.w = fmaf(n, fb.y, acc.w);
                }
            }
        }

        float4 hv = __ldg((const float4*)(h + (size_t)node * C) + g);
        float4 xv;
        xv.x = fmaf(gamma, acc.x, og * hv.x);
        xv.y = fmaf(gamma, acc.y, og * hv.y);
        xv.z = fmaf(gamma, acc.z, og * hv.z);
        xv.w = fmaf(gamma, acc.w, og * hv.w);
        ((float4*)(x + (size_t)node * C))[g] = xv;

        int c0 = g * 4;
        atomicAdd(&sstats[c0 + 0], xv.x);
        atomicAdd(&sstats[c0 + 1], xv.y);
        atomicAdd(&sstats[c0 + 2], xv.z);
        atomicAdd(&sstats[c0 + 3], xv.w);
        atomicAdd(&sstats[C + c0 + 0], xv.x * xv.x);
        atomicAdd(&sstats[C + c0 + 1], xv.y * xv.y);
        atomicAdd(&sstats[C + c0 + 2], xv.z * xv.z);
        atomicAdd(&sstats[C + c0 + 3], xv.w * xv.w);
    }
    __syncthreads();
    for (int i = tid; i < 2 * C; i += 256) atomicAdd(&stats[i], sstats[i]);
}

// ---------------- fold BN into affine (a,b) ----------------
template <int C>
__global__ void finalize_bn(const float* __restrict__ stats,
                            const float* __restrict__ scale,
                            const float* __restrict__ bias,
                            float* __restrict__ bn)
{
    int c = threadIdx.x;
    float mean = stats[c] * (1.0f / NN);
    float var = stats[C + c] * (1.0f / NN) - mean * mean;
    float inv = rsqrtf(var + 1e-5f);
    float a = __ldg(scale + c) * inv;
    bn[c] = a;
    bn[C + c] = __ldg(bias + c) - mean * a;
}

// ---------------- gather batch nodes + BN2 + relu + log_softmax ------------
__global__ __launch_bounds__(256) void out_kernel(
    const float* __restrict__ x2, const int* __restrict__ bnodes,
    const float* __restrict__ bn, float* __restrict__ out, int r)
{
    int idx = blockIdx.x * blockDim.x + threadIdx.x;
    int b = idx >> 5;
    int lane = idx & 31;
    if (b >= BB) return;
    int node = __ldg(bnodes + b);
    float v = x2[(size_t)node * OO + lane];
    v = fmaxf(0.f, fmaf(v, bn[lane], bn[OO + lane]));
    float m = v;
#pragma unroll
    for (int o = 16; o; o >>= 1) m = fmaxf(m, __shfl_xor_sync(0xffffffffu, m, o));
    float e = expf(v - m);
    float ssum = e;
#pragma unroll
    for (int o = 16; o; o >>= 1) ssum += __shfl_xor_sync(0xffffffffu, ssum, o);
    out[(size_t)b * (RR * OO) + r * OO + lane] = v - m - logf(ssum);
}

// ---------------- launcher ----------------
extern "C" void kernel_launch(void* const* d_in, const int* in_sizes, int n_in,
                              void* d_out, int out_size)
{
    const float* features    = (const float*)d_in[0];
    const int*   edge_index  = (const int*)d_in[1];
    const int*   batch_nodes = (const int*)d_in[2];
    const float* W1 = (const float*)d_in[3];
    const float* b1 = (const float*)d_in[4];
    const float* W2 = (const float*)d_in[5];
    const float* b2 = (const float*)d_in[6];
    const float* gamma1 = (const float*)d_in[7];
    const float* gamma2 = (const float*)d_in[8];
    const float* bn1s = (const float*)d_in[9];
    const float* bn1b = (const float*)d_in[10];
    const float* bn2s = (const float*)d_in[11];
    const float* bn2b = (const float*)d_in[12];
    float* out = (float*)d_out;

    void *p_z, *p_h1, *p_h1h, *p_x1, *p_h2, *p_h2h, *p_x2, *p_dinv,
         *p_rows, *p_cur, *p_bs, *p_csr, *p_bn;
    cudaGetSymbolAddress(&p_z, g_z);
    cudaGetSymbolAddress(&p_h1, g_h1);
    cudaGetSymbolAddress(&p_h1h, g_h1h);
    cudaGetSymbolAddress(&p_x1, g_x1);
    cudaGetSymbolAddress(&p_h2, g_h2);
    cudaGetSymbolAddress(&p_h2h, g_h2h);
    cudaGetSymbolAddress(&p_x2, g_x2);
    cudaGetSymbolAddress(&p_dinv, g_dinv);
    cudaGetSymbolAddress(&p_rows, g_rowstart);
    cudaGetSymbolAddress(&p_cur, g_cursor);
    cudaGetSymbolAddress(&p_bs, g_bsums);
    cudaGetSymbolAddress(&p_csr, g_csr);
    cudaGetSymbolAddress(&p_bn, g_bn);

    int*   z_deg    = (int*)p_z;
    int*   z_sync   = (int*)((char*)p_z + offsetof(ZeroBlk, sync));
    float* z_stats1 = (float*)((char*)p_z + offsetof(ZeroBlk, stats1));
    float* z_stats2 = (float*)((char*)p_z + offsetof(ZeroBlk, stats2));

    const int GEMM_GRID = (NN + 255) / 256;   // 391

    for (int r = 0; r < RR; r++) {
        const int* src = edge_index + (size_t)r * 2 * EE;
        const int* dst = src + EE;

        cudaMemsetAsync(p_z, 0, sizeof(ZeroBlk));
        degree_kernel<<<(EE / 4 + 255) / 256, 256>>>(dst, z_deg);
        scan_fused<<<SCAN_BLKS, 1024>>>(z_deg, (float*)p_dinv, (int*)p_rows,
                                        (int*)p_cur, (int*)p_bs, z_sync);
        fill_csr<<<(EE + 255) / 256, 256>>>(src, dst, (const float*)p_dinv,
                                            (int*)p_cur, (ull*)p_csr);
        // conv1 linear (+ fp16 sidecar)
        gemm_tiled<FF, HH, false><<<GEMM_GRID, 256>>>(
            features, W1 + (size_t)r * FF * HH, b1 + r * HH, nullptr,
            (float*)p_h1, (__half*)p_h1h, NN);
        // conv1 aggregate + combine + BN1 stats
        gather_combine<HH><<<(NN + 15) / 16, 256>>>(
            (const float*)p_h1, (const __half*)p_h1h, (const ull*)p_csr,
            (const int*)p_rows, z_deg, gamma1, r,
            (float*)p_x1, z_stats1);
        finalize_bn<HH><<<1, HH>>>(z_stats1, bn1s + r * HH, bn1b + r * HH,
                                   (float*)p_bn);
        // conv2 linear with fused BN1-apply + relu on input (+ fp16 sidecar)
        gemm_tiled<HH, OO, true><<<GEMM_GRID, 256>>>(
            (const float*)p_x1, W2 + (size_t)r * HH * OO, b2 + r * OO,
            (const float*)p_bn, (float*)p_h2, (__half*)p_h2h, NN);
        // conv2 aggregate + combine + BN2 stats
        gather_combine<OO><<<(NN + 31) / 32, 256>>>(
            (const float*)p_h2, (const __half*)p_h2h, (const ull*)p_csr,
            (const int*)p_rows, z_deg, gamma2, r,
            (float*)p_x2, z_stats2);
        finalize_bn<OO><<<1, OO>>>(z_stats2, bn2s + r * OO, bn2b + r * OO,
                                   (float*)p_bn);
        out_kernel<<<(BB * 32 + 255) / 256, 256>>>(
            (const float*)p_x2, batch_nodes, (const float*)p_bn, out, r);
    }
}

// round 11
// speedup vs baseline: 1.9030x; 1.0541x over previous
#include <cuda_runtime.h>
#include <cuda_fp16.h>

#define NN 100000
#define EE 1600000
#define RR 3
#define FF 128
#define HH 64
#define OO 32
#define BB 50000
#define SCAN_BLKS ((NN + 1023) / 1024)

typedef unsigned long long ull;

// ---------------- scratch ----------------
struct BuildBuf {                 // double-buffered per-relation CSR state
    int deg[NN];
};
__device__ BuildBuf g_bb[2];
__device__ int    g_rowstart2[2][NN];
__device__ ull    g_csr2[2][EE];     // packed (src:int low32, norm:float high32)
__device__ float  g_dinv[NN];        // build-internal (serial on build stream)
__device__ int    g_cursor[NN];
__device__ int    g_bsums[SCAN_BLKS];
__device__ float  g_h1[NN * HH];
__device__ __half g_h1h[NN * HH];
__device__ float  g_x1[NN * HH];
__device__ float  g_h2[NN * OO];
__device__ __half g_h2h[NN * OO];
__device__ float  g_x2[NN * OO];
__device__ float  g_stats[2 * HH];
__device__ float  g_bn[2 * HH];

// ---------------- f32x2 helpers ----------------
__device__ __forceinline__ ull fma2(ull a, ull b, ull c)
{
    ull d;
    asm("fma.rn.f32x2 %0, %1, %2, %3;" : "=l"(d) : "l"(a), "l"(b), "l"(c));
    return d;
}
__device__ __forceinline__ ull pack2(float x, float y)
{
    ull d;
    asm("mov.b64 %0, {%1,%2};" : "=l"(d) : "f"(x), "f"(y));
    return d;
}

// ---------------- tiled GEMM: Y = act(X) @ W + b ; also emits fp16 copy ----
template <int K, int C, bool FUSE>
__global__ __launch_bounds__(256, 2) void gemm_tiled(
    const float* __restrict__ X, const float* __restrict__ Wg,
    const float* __restrict__ bg, const float* __restrict__ bnp,
    float* __restrict__ Y, __half* __restrict__ Yh, int nrows)
{
    constexpr int KB = 32;
    constexpr int CPT = C / 8;
    constexpr int NC2 = CPT / 2;
    __shared__ float sXT[KB][256];
    __shared__ float sW[KB][C];

    int tid = threadIdx.x;
    int rg = tid >> 3;
    int cg = tid & 7;
    int row0 = blockIdx.x * 256;
    int myrow = row0 + tid;
    bool valid = myrow < nrows;

    ull acc[8][NC2];
    {
        const ull* bp = (const ull*)(bg + cg * CPT);
#pragma unroll
        for (int j = 0; j < NC2; j++) {
            ull bv = __ldg(bp + j);
#pragma unroll
            for (int rr = 0; rr < 8; rr++) acc[rr][j] = bv;
        }
    }

    const float4* Xr = (const float4*)(X + (size_t)myrow * K);

    for (int kc = 0; kc < K; kc += KB) {
        {
            const float4* Wt = (const float4*)(Wg + (size_t)kc * C);
#pragma unroll
            for (int i = tid; i < KB * C / 4; i += 256)
                ((float4*)&sW[0][0])[i] = __ldg(Wt + i);
        }
#pragma unroll
        for (int j4 = 0; j4 < KB / 4; j4++) {
            float4 v = valid ? __ldg(Xr + kc / 4 + j4)
                             : make_float4(0.f, 0.f, 0.f, 0.f);
            if (FUSE) {
                float4 a = __ldg((const float4*)bnp + kc / 4 + j4);
                float4 b = __ldg((const float4*)(bnp + K) + kc / 4 + j4);
                v.x = fmaxf(0.f, fmaf(v.x, a.x, b.x));
                v.y = fmaxf(0.f, fmaf(v.y, a.y, b.y));
                v.z = fmaxf(0.f, fmaf(v.z, a.z, b.z));
                v.w = fmaxf(0.f, fmaf(v.w, a.w, b.w));
            }
            sXT[j4 * 4 + 0][tid] = v.x;
            sXT[j4 * 4 + 1][tid] = v.y;
            sXT[j4 * 4 + 2][tid] = v.z;
            sXT[j4 * 4 + 3][tid] = v.w;
        }
        __syncthreads();

#pragma unroll
        for (int k = 0; k < KB; k++) {
            float x[8];
            *(float4*)&x[0] = *(const float4*)&sXT[k][rg * 8];
            *(float4*)&x[4] = *(const float4*)&sXT[k][rg * 8 + 4];
            ull w2[NC2];
#pragma unroll
            for (int j2 = 0; j2 < NC2 / 2; j2++) {
                ulonglong2 wv = *(const ulonglong2*)&sW[k][cg * CPT + j2 * 4];
                w2[2 * j2] = wv.x;
                w2[2 * j2 + 1] = wv.y;
            }
#pragma unroll
            for (int rr = 0; rr < 8; rr++) {
                ull xx = pack2(x[rr], x[rr]);
#pragma unroll
                for (int j = 0; j < NC2; j++)
                    acc[rr][j] = fma2(xx, w2[j], acc[rr][j]);
            }
        }
        __syncthreads();
    }

#pragma unroll
    for (int rr = 0; rr < 8; rr++) {
        int row = row0 + rg * 8 + rr;
        if (row < nrows) {
            ull* Yp = (ull*)(Y + (size_t)row * C + cg * CPT);
#pragma unroll
            for (int j2 = 0; j2 < NC2 / 2; j2++) {
                ulonglong2 o;
                o.x = acc[rr][2 * j2];
                o.y = acc[rr][2 * j2 + 1];
                *(ulonglong2*)(Yp + 2 * j2) = o;
            }
            unsigned hp[NC2];
#pragma unroll
            for (int j = 0; j < NC2; j++) {
                float lo = __uint_as_float((unsigned)acc[rr][j]);
                float hi = __uint_as_float((unsigned)(acc[rr][j] >> 32));
                __half2 h2 = __floats2half2_rn(lo, hi);
                hp[j] = *(unsigned*)&h2;
            }
            __half* Yhp = Yh + (size_t)row * C + cg * CPT;
            if (NC2 == 4) {
                uint4 o4;
                o4.x = hp[0]; o4.y = hp[1]; o4.z = hp[2]; o4.w = hp[3];
                *(uint4*)Yhp = o4;
            } else {
                uint2 o2;
                o2.x = hp[0]; o2.y = hp[1];
                *(uint2*)Yhp = o2;
            }
        }
    }
}

// ---------------- degree (int4 vectorized) ----------------
__global__ __launch_bounds__(256) void degree_kernel(
    const int* __restrict__ dst, int* __restrict__ deg)
{
    int e4 = blockIdx.x * blockDim.x + threadIdx.x;
    if (e4 < EE / 4) {
        int4 d = __ldg((const int4*)dst + e4);
        atomicAdd(deg + d.x, 1);
        atomicAdd(deg + d.y, 1);
        atomicAdd(deg + d.z, 1);
        atomicAdd(deg + d.w, 1);
    }
}

__global__ void dinv_kernel(const int* __restrict__ deg, float* __restrict__ dinv)
{
    int i = blockIdx.x * blockDim.x + threadIdx.x;
    if (i < NN) dinv[i] = rsqrtf(fmaxf((float)deg[i], 1.0f));
}

// ---------------- 3-kernel scan (deadlock-free under co-residency) --------
__global__ __launch_bounds__(1024) void scan_block(
    const int* __restrict__ deg, int* __restrict__ out, int* __restrict__ bsums)
{
    __shared__ int sh[1024];
    int i = blockIdx.x * 1024 + threadIdx.x;
    int v = (i < NN) ? deg[i] : 0;
    sh[threadIdx.x] = v;
    __syncthreads();
#pragma unroll
    for (int off = 1; off < 1024; off <<= 1) {
        int t = (threadIdx.x >= off) ? sh[threadIdx.x - off] : 0;
        __syncthreads();
        sh[threadIdx.x] += t;
        __syncthreads();
    }
    if (i < NN) out[i] = sh[threadIdx.x] - v;
    if (threadIdx.x == 1023) bsums[blockIdx.x] = sh[1023];
}

__global__ void scan_sums(int* __restrict__ bsums)
{
    if (threadIdx.x == 0) {
        int acc = 0;
        for (int i = 0; i < SCAN_BLKS; i++) {
            int t = bsums[i]; bsums[i] = acc; acc += t;
        }
    }
}

__global__ __launch_bounds__(1024) void scan_add(
    int* __restrict__ out, const int* __restrict__ bsums, int* __restrict__ cursor)
{
    int i = blockIdx.x * 1024 + threadIdx.x;
    if (i < NN) {
        int v = out[i] + bsums[blockIdx.x];
        out[i] = v;
        cursor[i] = v;
    }
}

// ---------------- fill CSR (packed 8B entries) ----------------
__global__ __launch_bounds__(256) void fill_csr(
    const int* __restrict__ src, const int* __restrict__ dst,
    const float* __restrict__ dinv, int* __restrict__ cursor,
    ull* __restrict__ csr)
{
    int e = blockIdx.x * blockDim.x + threadIdx.x;
    if (e >= EE) return;
    int s = __ldg(src + e);
    int d = __ldg(dst + e);
    int pos = atomicAdd(cursor + d, 1);
    float norm = __ldg(dinv + s) * __ldg(dinv + d);
    csr[pos] = (ull)(unsigned)s | ((ull)__float_as_uint(norm) << 32);
}

// ---------------- fused gather(fp16 neighbors) + combine + BN stats --------
template <int C>
__global__ __launch_bounds__(256) void gather_combine(
    const float* __restrict__ h, const __half* __restrict__ hh,
    const ull* __restrict__ csr,
    const int* __restrict__ row_start, const int* __restrict__ deg,
    const float* __restrict__ gammaArr, int r,
    float* __restrict__ x, float* __restrict__ stats)
{
    constexpr int GPN = C / 4;
    constexpr int NPB = 256 / GPN;
    __shared__ float sstats[2 * C];
    int tid = threadIdx.x;
    for (int i = tid; i < 2 * C; i += 256) sstats[i] = 0.f;
    __syncthreads();

    int g = tid & (GPN - 1);
    int node = blockIdx.x * NPB + tid / GPN;
    unsigned gmask = ((1u << GPN) - 1u) << ((tid & 31) & ~(GPN - 1));

    if (node < NN) {
        float gamma = __ldg(gammaArr + r);
        float og = 1.0f - gamma;
        int start = __ldg(row_start + node);
        int d = __ldg(deg + node);
        float4 acc = make_float4(0.f, 0.f, 0.f, 0.f);

        for (int base = 0; base < d; base += GPN) {
            int cnt = min(GPN, d - base);
            ull p = 0;
            if (g < cnt) p = __ldg(csr + start + base + g);
            if (cnt == GPN) {
#pragma unroll
                for (int j = 0; j < GPN; j++) {
                    ull pj = __shfl_sync(gmask, p, j, GPN);
                    int s = (int)(unsigned)pj;
                    float n = __uint_as_float((unsigned)(pj >> 32));
                    uint2 hv2 = __ldg((const uint2*)(hh + (size_t)s * C) + g);
                    float2 fa = __half22float2(*(__half2*)&hv2.x);
                    float2 fb = __half22float2(*(__half2*)&hv2.y);
                    acc.x = fmaf(n, fa.x, acc.x);
                    acc.y = fmaf(n, fa.y, acc.y);
                    acc.z = fmaf(n, fb.x, acc.z);
                    acc.w = fmaf(n, fb.y, acc.w);
                }
            } else {
                for (int j = 0; j < cnt; j++) {
                    ull pj = __shfl_sync(gmask, p, j, GPN);
                    int s = (int)(unsigned)pj;
                    float n = __uint_as_float((unsigned)(pj >> 32));
                    uint2 hv2 = __ldg((const uint2*)(hh + (size_t)s * C) + g);
                    float2 fa = __half22float2(*(__half2*)&hv2.x);
                    float2 fb = __half22float2(*(__half2*)&hv2.y);
                    acc.x = fmaf(n, fa.x, acc.x);
                    acc.y = fmaf(n, fa.y, acc.y);
                    acc.z = fmaf(n, fb.x, acc.z);
                    acc.w = fmaf(n, fb.y, acc.w);
                }
            }
        }

        float4 hv = __ldg((const float4*)(h + (size_t)node * C) + g);
        float4 xv;
        xv.x = fmaf(gamma, acc.x, og * hv.x);
        xv.y = fmaf(gamma, acc.y, og * hv.y);
        xv.z = fmaf(gamma, acc.z, og * hv.z);
        xv.w = fmaf(gamma, acc.w, og * hv.w);
        ((float4*)(x + (size_t)node * C))[g] = xv;

        int c0 = g * 4;
        atomicAdd(&sstats[c0 + 0], xv.x);
        atomicAdd(&sstats[c0 + 1], xv.y);
        atomicAdd(&sstats[c0 + 2], xv.z);
        atomicAdd(&sstats[c0 + 3], xv.w);
        atomicAdd(&sstats[C + c0 + 0], xv.x * xv.x);
        atomicAdd(&sstats[C + c0 + 1], xv.y * xv.y);
        atomicAdd(&sstats[C + c0 + 2], xv.z * xv.z);
        atomicAdd(&sstats[C + c0 + 3], xv.w * xv.w);
    }
    __syncthreads();
    for (int i = tid; i < 2 * C; i += 256) atomicAdd(&stats[i], sstats[i]);
}

// ---------------- fold BN into affine (a,b) ----------------
template <int C>
__global__ void finalize_bn(const float* __restrict__ stats,
                            const float* __restrict__ scale,
                            const float* __restrict__ bias,
                            float* __restrict__ bn)
{
    int c = threadIdx.x;
    float mean = stats[c] * (1.0f / NN);
    float var = stats[C + c] * (1.0f / NN) - mean * mean;
    float inv = rsqrtf(var + 1e-5f);
    float a = __ldg(scale + c) * inv;
    bn[c] = a;
    bn[C + c] = __ldg(bias + c) - mean * a;
}

// ---------------- gather batch nodes + BN2 + relu + log_softmax ------------
__global__ __launch_bounds__(256) void out_kernel(
    const float* __restrict__ x2, const int* __restrict__ bnodes,
    const float* __restrict__ bn, float* __restrict__ out, int r)
{
    int idx = blockIdx.x * blockDim.x + threadIdx.x;
    int b = idx >> 5;
    int lane = idx & 31;
    if (b >= BB) return;
    int node = __ldg(bnodes + b);
    float v = x2[(size_t)node * OO + lane];
    v = fmaxf(0.f, fmaf(v, bn[lane], bn[OO + lane]));
    float m = v;
#pragma unroll
    for (int o = 16; o; o >>= 1) m = fmaxf(m, __shfl_xor_sync(0xffffffffu, m, o));
    float e = expf(v - m);
    float ssum = e;
#pragma unroll
    for (int o = 16; o; o >>= 1) ssum += __shfl_xor_sync(0xffffffffu, ssum, o);
    out[(size_t)b * (RR * OO) + r * OO + lane] = v - m - logf(ssum);
}

// ---------------- launcher ----------------
static void build_csr_rel(int r, int b, const int* edge_index,
                          void* p_bb, void* p_rows2, void* p_csr2,
                          void* p_dinv, void* p_cur, void* p_bs,
                          cudaStream_t s)
{
    const int* src = edge_index + (size_t)r * 2 * EE;
    const int* dst = src + EE;
    int* deg  = (int*)((char*)p_bb + (size_t)b * sizeof(BuildBuf));
    int* rows = (int*)((char*)p_rows2 + (size_t)b * NN * sizeof(int));
    ull* csr  = (ull*)((char*)p_csr2 + (size_t)b * EE * sizeof(ull));

    cudaMemsetAsync(deg, 0, NN * sizeof(int), s);
    degree_kernel<<<(EE / 4 + 255) / 256, 256, 0, s>>>(dst, deg);
    dinv_kernel<<<(NN + 255) / 256, 256, 0, s>>>(deg, (float*)p_dinv);
    scan_block<<<SCAN_BLKS, 1024, 0, s>>>(deg, rows, (int*)p_bs);
    scan_sums<<<1, 32, 0, s>>>((int*)p_bs);
    scan_add<<<SCAN_BLKS, 1024, 0, s>>>(rows, (const int*)p_bs, (int*)p_cur);
    fill_csr<<<(EE + 255) / 256, 256, 0, s>>>(src, dst, (const float*)p_dinv,
                                              (int*)p_cur, csr);
}

extern "C" void kernel_launch(void* const* d_in, const int* in_sizes, int n_in,
                              void* d_out, int out_size)
{
    const float* features    = (const float*)d_in[0];
    const int*   edge_index  = (const int*)d_in[1];
    const int*   batch_nodes = (const int*)d_in[2];
    const float* W1 = (const float*)d_in[3];
    const float* b1 = (const float*)d_in[4];
    const float* W2 = (const float*)d_in[5];
    const float* b2 = (const float*)d_in[6];
    const float* gamma1 = (const float*)d_in[7];
    const float* gamma2 = (const float*)d_in[8];
    const float* bn1s = (const float*)d_in[9];
    const float* bn1b = (const float*)d_in[10];
    const float* bn2s = (const float*)d_in[11];
    const float* bn2b = (const float*)d_in[12];
    float* out = (float*)d_out;

    static cudaStream_t sB = nullptr;
    static cudaEvent_t e_fork, evC[RR], evG0;
    if (sB == nullptr) {
        cudaStreamCreateWithFlags(&sB, cudaStreamNonBlocking);
        cudaEventCreateWithFlags(&e_fork, cudaEventDisableTiming);
        cudaEventCreateWithFlags(&evG0, cudaEventDisableTiming);
        for (int i = 0; i < RR; i++)
            cudaEventCreateWithFlags(&evC[i], cudaEventDisableTiming);
    }

    void *p_bb, *p_rows2, *p_csr2, *p_dinv, *p_cur, *p_bs,
         *p_h1, *p_h1h, *p_x1, *p_h2, *p_h2h, *p_x2, *p_stats, *p_bn;
    cudaGetSymbolAddress(&p_bb, g_bb);
    cudaGetSymbolAddress(&p_rows2, g_rowstart2);
    cudaGetSymbolAddress(&p_csr2, g_csr2);
    cudaGetSymbolAddress(&p_dinv, g_dinv);
    cudaGetSymbolAddress(&p_cur, g_cursor);
    cudaGetSymbolAddress(&p_bs, g_bsums);
    cudaGetSymbolAddress(&p_h1, g_h1);
    cudaGetSymbolAddress(&p_h1h, g_h1h);
    cudaGetSymbolAddress(&p_x1, g_x1);
    cudaGetSymbolAddress(&p_h2, g_h2);
    cudaGetSymbolAddress(&p_h2h, g_h2h);
    cudaGetSymbolAddress(&p_x2, g_x2);
    cudaGetSymbolAddress(&p_stats, g_stats);
    cudaGetSymbolAddress(&p_bn, g_bn);

    const int GEMM_GRID = (NN + 255) / 256;

    // fork build stream off the capture stream
    cudaEventRecord(e_fork, 0);
    cudaStreamWaitEvent(sB, e_fork, 0);

    // builds 0 and 1 (independent buffers) up front on sB
    build_csr_rel(0, 0, edge_index, p_bb, p_rows2, p_csr2, p_dinv, p_cur, p_bs, sB);
    cudaEventRecord(evC[0], sB);
    build_csr_rel(1, 1, edge_index, p_bb, p_rows2, p_csr2, p_dinv, p_cur, p_bs, sB);
    cudaEventRecord(evC[1], sB);

    for (int r = 0; r < RR; r++) {
        int b = r & 1;
        int* deg  = (int*)((char*)p_bb + (size_t)b * sizeof(BuildBuf));
        int* rows = (int*)((char*)p_rows2 + (size_t)b * NN * sizeof(int));
        ull* csr  = (ull*)((char*)p_csr2 + (size_t)b * EE * sizeof(ull));

        // conv1 linear (+ fp16 sidecar) — independent of CSR
        gemm_tiled<FF, HH, false><<<GEMM_GRID, 256>>>(
            features, W1 + (size_t)r * FF * HH, b1 + r * HH, nullptr,
            (float*)p_h1, (__half*)p_h1h, NN);

        cudaStreamWaitEvent(0, evC[r], 0);
        cudaMemsetAsync(p_stats, 0, 2 * HH * sizeof(float), 0);

        gather_combine<HH><<<(NN + 15) / 16, 256>>>(
            (const float*)p_h1, (const __half*)p_h1h, (const ull*)csr,
            (const int*)rows, deg, gamma1, r,
            (float*)p_x1, (float*)p_stats);
        finalize_bn<HH><<<1, HH>>>((const float*)p_stats, bn1s + r * HH,
                                   bn1b + r * HH, (float*)p_bn);

        if (r == 0) {
            // buffer 0 fully consumed after gather1? no — gather2 also reads csr.
            // record AFTER last consumer below; see evG0 record position.
        }

        gemm_tiled<HH, OO, true><<<GEMM_GRID, 256>>>(
            (const float*)p_x1, W2 + (size_t)r * HH * OO, b2 + r * OO,
            (const float*)p_bn, (float*)p_h2, (__half*)p_h2h, NN);

        cudaMemsetAsync(p_stats, 0, 2 * OO * sizeof(float), 0);
        gather_combine<OO><<<(NN + 31) / 32, 256>>>(
            (const float*)p_h2, (const __half*)p_h2h, (const ull*)csr,
            (const int*)rows, deg, gamma2, r,
            (float*)p_x2, (float*)p_stats);
        finalize_bn<OO><<<1, OO>>>((const float*)p_stats, bn2s + r * OO,
                                   bn2b + r * OO, (float*)p_bn);

        out_kernel<<<(BB * 32 + 255) / 256, 256>>>(
            (const float*)p_x2, batch_nodes, (const float*)p_bn, out, r);

        if (r == 0) {
            // buffer 0's last consumer (gather_combine<OO>) is enqueued;
            // release it for build 2 and enqueue build 2 NOW so its wait
            // references an event already recorded in this capture.
            cudaEventRecord(evG0, 0);
            cudaStreamWaitEvent(sB, evG0, 0);
            build_csr_rel(2, 0, edge_index, p_bb, p_rows2, p_csr2,
                          p_dinv, p_cur, p_bs, sB);
            cudaEventRecord(evC[2], sB);
        }
    }
}